// round 7
// baseline (speedup 1.0000x reference)
#include <cuda_runtime.h>
#include <cuda_bf16.h>
#include <math.h>
#include <stdint.h>

#define BB 4
#define TT 2048
#define DD 1024
#define HH 16
#define HD 64
#define MTOT (BB*TT)   // 8192

// ---------------- scratch (device globals: allocation-free) ----------------
__device__ float g_q [MTOT*DD];
__device__ float g_k [MTOT*DD];
__device__ float g_v [MTOT*DD];

__device__ __nv_bfloat16 g_xh [MTOT*DD];
__device__ __nv_bfloat16 g_xl [MTOT*DD];
__device__ __nv_bfloat16 g_aoh[MTOT*DD];
__device__ __nv_bfloat16 g_aol[MTOT*DD];
__device__ __nv_bfloat16 g_wh [4*DD*DD];
__device__ __nv_bfloat16 g_wl [4*DD*DD];

// attention operands (bf16 hi/lo)
__device__ __nv_bfloat16 g_qh [MTOT*DD];
__device__ __nv_bfloat16 g_ql [MTOT*DD];
__device__ __nv_bfloat16 g_kh [MTOT*DD];
__device__ __nv_bfloat16 g_kl [MTOT*DD];
__device__ __nv_bfloat16 g_vth[MTOT*DD];   // [b][h][d][T]
__device__ __nv_bfloat16 g_vtl[MTOT*DD];

// =============================== PTX helpers ===============================
__device__ __forceinline__ uint32_t smem_u32(const void* p) {
    uint32_t a;
    asm("{ .reg .u64 t; cvta.to.shared.u64 t, %1; cvt.u32.u64 %0, t; }" : "=r"(a) : "l"(p));
    return a;
}

#define LDSM4(r, a) \
    asm volatile("ldmatrix.sync.aligned.m8n8.x4.shared.b16 {%0,%1,%2,%3}, [%4];" \
        : "=r"((r)[0]), "=r"((r)[1]), "=r"((r)[2]), "=r"((r)[3]) : "r"(a))

#define MMA16816(d, a, b0, b1) \
    asm volatile("mma.sync.aligned.m16n8k16.row.col.f32.bf16.bf16.f32 " \
        "{%0,%1,%2,%3}, {%4,%5,%6,%7}, {%8,%9}, {%0,%1,%2,%3};" \
        : "+f"((d)[0]), "+f"((d)[1]), "+f"((d)[2]), "+f"((d)[3]) \
        : "r"((a)[0]), "r"((a)[1]), "r"((a)[2]), "r"((a)[3]), "r"(b0), "r"(b1))

#define CP_ASYNC16(dst, src) \
    asm volatile("cp.async.cg.shared.global [%0], [%1], 16;" :: "r"(dst), "l"(src))
#define CP_COMMIT() asm volatile("cp.async.commit_group;" ::: "memory")
#define CP_WAIT0()  asm volatile("cp.async.wait_group 0;" ::: "memory")

// fast exp on fma/alu pipes (valid for x in [-80, 30])
__device__ __forceinline__ float fexp(float x) {
    x = fmaxf(x, -80.f);
    float z  = x * 1.4426950408889634f;
    float zi = z + 12582912.f;
    float fi = zi - 12582912.f;
    float f  = z - fi;
    int   ei = __float_as_int(zi);
    float p = 0.00133335581f;
    p = fmaf(p, f, 0.00961812911f);
    p = fmaf(p, f, 0.05550410866f);
    p = fmaf(p, f, 0.24022650700f);
    p = fmaf(p, f, 0.69314718056f);
    p = fmaf(p, f, 1.0f);
    return __int_as_float(__float_as_int(p) + (ei << 23));
}

__device__ __forceinline__ uint32_t pack_bf2(float a, float b) {
    __nv_bfloat162 h = __float22bfloat162_rn(make_float2(a, b));
    return *(uint32_t*)&h;
}

// split 8 floats -> hi/lo uint4
__device__ __forceinline__ void split8(const float4 a, const float4 b,
                                       uint4* H, uint4* L) {
    uint32_t h0 = pack_bf2(a.x, a.y), h1 = pack_bf2(a.z, a.w);
    uint32_t h2 = pack_bf2(b.x, b.y), h3 = pack_bf2(b.z, b.w);
    float2 r0 = __bfloat1622float2(*(__nv_bfloat162*)&h0);
    float2 r1 = __bfloat1622float2(*(__nv_bfloat162*)&h1);
    float2 r2 = __bfloat1622float2(*(__nv_bfloat162*)&h2);
    float2 r3 = __bfloat1622float2(*(__nv_bfloat162*)&h3);
    *H = make_uint4(h0, h1, h2, h3);
    *L = make_uint4(pack_bf2(a.x - r0.x, a.y - r0.y),
                    pack_bf2(a.z - r1.x, a.w - r1.y),
                    pack_bf2(b.x - r2.x, b.y - r2.y),
                    pack_bf2(b.z - r3.x, b.w - r3.y));
}

// ===========================================================================
// split_all: x + 4 weights -> hi/lo bf16 in one launch. grid 6144 x 256.
// ===========================================================================
#define XU (MTOT * DD / 8)
#define WU (DD * DD / 8)

__global__ __launch_bounds__(256) void split_all(const float* __restrict__ x,
                                                 const float* __restrict__ wq,
                                                 const float* __restrict__ wk,
                                                 const float* __restrict__ wv,
                                                 const float* __restrict__ wo) {
    size_t u = (size_t)blockIdx.x * 256 + threadIdx.x;
    const float* src;
    __nv_bfloat16 *H, *L;
    size_t off;
    if (u < XU) {
        src = x; H = g_xh; L = g_xl; off = u;
    } else {
        size_t r = u - XU;
        int w = (int)(r / WU);
        off = r % WU;
        src = (w == 0) ? wq : (w == 1) ? wk : (w == 2) ? wv : wo;
        H = g_wh + (size_t)w * DD * DD;
        L = g_wl + (size_t)w * DD * DD;
    }
    float4 a = ((const float4*)src)[2 * off];
    float4 b = ((const float4*)src)[2 * off + 1];
    uint4 hv, lv;
    split8(a, b, &hv, &lv);
    ((uint4*)H)[off] = hv;
    ((uint4*)L)[off] = lv;
}

// ===========================================================================
// big-tile split-bf16 GEMM: CTA 256x128, 8 warps (4M x 2N), warp 64x64,
// K-chunk 32, 2-stage cp.async. grid (8, 32, nw).
// ===========================================================================
#define G2_ROWB  80
#define G2_ATILE (256 * G2_ROWB)          // 20480
#define G2_BTILE (128 * G2_ROWB)          // 10240
#define G2_STAGE (2 * G2_ATILE + 2 * G2_BTILE)   // 61440
#define G2_SMEM  (2 * G2_STAGE)           // 122880

__global__ __launch_bounds__(256) void gemm_big(const __nv_bfloat16* __restrict__ Ah,
                                                const __nv_bfloat16* __restrict__ Al,
                                                const __nv_bfloat16* __restrict__ Wh,
                                                const __nv_bfloat16* __restrict__ Wl,
                                                float* __restrict__ C0,
                                                float* __restrict__ C1,
                                                float* __restrict__ C2) {
    extern __shared__ char smem[];
    const uint32_t sb = smem_u32(smem);
    const int tid  = threadIdx.x;
    const int wid  = tid >> 5;
    const int lane = tid & 31;
    const int wm   = wid & 3;
    const int wn   = wid >> 2;
    const int bn   = blockIdx.x * 128;
    const int bm   = blockIdx.y * 256;
    const int w    = blockIdx.z;

    const char* gAh = (const char*)Ah + (size_t)bm * 2048;
    const char* gAl = (const char*)Al + (size_t)bm * 2048;
    const char* gBh = (const char*)(Wh + (size_t)w * DD * DD) + (size_t)bn * 2048;
    const char* gBl = (const char*)(Wl + (size_t)w * DD * DD) + (size_t)bn * 2048;
    float* C = (w == 0) ? C0 : (w == 1) ? C1 : C2;

    auto issue_copy = [&](int kc, int s) {
        uint32_t base = sb + s * G2_STAGE;
#pragma unroll
        for (int i = 0; i < 12; i++) {
            int u = tid + 256 * i;           // 0..3071
            uint32_t dst;
            const char* src;
            if (u < 2048) {                  // A tiles (Ah, Al)
                int t = u >> 10, v = u & 1023;
                int r = v >> 2, c = v & 3;
                dst = base + t * G2_ATILE + r * G2_ROWB + c * 16;
                src = (t ? gAl : gAh) + (size_t)r * 2048 + kc * 64 + c * 16;
            } else {                          // B tiles (Bh, Bl)
                int t = (u - 2048) >> 9, v = u & 511;
                int r = v >> 2, c = v & 3;
                dst = base + 2 * G2_ATILE + t * G2_BTILE + r * G2_ROWB + c * 16;
                src = (t ? gBl : gBh) + (size_t)r * 2048 + kc * 64 + c * 16;
            }
            CP_ASYNC16(dst, src);
        }
        CP_COMMIT();
    };

    float acc[4][8][4];
#pragma unroll
    for (int m = 0; m < 4; m++)
#pragma unroll
        for (int j = 0; j < 8; j++)
#pragma unroll
            for (int e = 0; e < 4; e++) acc[m][j][e] = 0.f;

    const int m8  = (lane >> 3) & 1, k8a = lane >> 4;
    const int n8  = lane >> 4,       k8b = (lane >> 3) & 1;
    const int la7 = lane & 7;

    auto compute = [&](int s) {
        uint32_t ahB = sb + s * G2_STAGE;
        uint32_t alB = ahB + G2_ATILE;
        uint32_t bhB = alB + G2_ATILE;
        uint32_t blB = bhB + G2_BTILE;
#pragma unroll
        for (int k16 = 0; k16 < 2; k16++) {
            int colA = k16 * 32 + k8a * 16;
            int colB = k16 * 32 + k8b * 16;
            uint32_t ah[4][4], al[4][4];
#pragma unroll
            for (int m = 0; m < 4; m++) {
                int row = wm * 64 + m * 16 + m8 * 8 + la7;
                LDSM4(ah[m], ahB + row * G2_ROWB + colA);
                LDSM4(al[m], alB + row * G2_ROWB + colA);
            }
#pragma unroll
            for (int jp = 0; jp < 4; jp++) {
                int row = wn * 64 + jp * 16 + n8 * 8 + la7;
                uint32_t bh4[4], bl4[4];
                LDSM4(bh4, bhB + row * G2_ROWB + colB);
                LDSM4(bl4, blB + row * G2_ROWB + colB);
#pragma unroll
                for (int m = 0; m < 4; m++) {
                    MMA16816(acc[m][2 * jp],     ah[m], bh4[0], bh4[1]);
                    MMA16816(acc[m][2 * jp + 1], ah[m], bh4[2], bh4[3]);
                    MMA16816(acc[m][2 * jp],     ah[m], bl4[0], bl4[1]);
                    MMA16816(acc[m][2 * jp + 1], ah[m], bl4[2], bl4[3]);
                    MMA16816(acc[m][2 * jp],     al[m], bh4[0], bh4[1]);
                    MMA16816(acc[m][2 * jp + 1], al[m], bh4[2], bh4[3]);
                }
            }
        }
    };

    issue_copy(0, 0);
    for (int c = 0; c < 32; c++) {
        CP_WAIT0();
        __syncthreads();
        if (c < 31) issue_copy(c + 1, (c + 1) & 1);
        compute(c & 1);
    }

    const int r0 = bm + wm * 64 + (lane >> 2);
    const int c0 = bn + wn * 64 + (lane & 3) * 2;
#pragma unroll
    for (int m = 0; m < 4; m++)
#pragma unroll
        for (int j = 0; j < 8; j++) {
            float* p0 = C + (size_t)(r0 + m * 16) * 1024 + c0 + j * 8;
            float* p1 = C + (size_t)(r0 + m * 16 + 8) * 1024 + c0 + j * 8;
            *(float2*)p0 = make_float2(acc[m][j][0], acc[m][j][1]);
            *(float2*)p1 = make_float2(acc[m][j][2], acc[m][j][3]);
        }
}

// ===========================================================================
// prep: fused RoPE+split (blocks 0..8191) and V split+transpose (8192..10239)
// ===========================================================================
__global__ __launch_bounds__(256) void prep_kernel(const int* __restrict__ pos) {
    __shared__ float vs[64][65];
    const int tid = threadIdx.x;

    if (blockIdx.x < MTOT) {
        const int bt = blockIdx.x;
        const float p = (float)pos[bt];
        const float* q = g_q + (size_t)bt * DD;
        const float* k = g_k + (size_t)bt * DD;
        __nv_bfloat162* qh = (__nv_bfloat162*)(g_qh + (size_t)bt * DD);
        __nv_bfloat162* ql = (__nv_bfloat162*)(g_ql + (size_t)bt * DD);
        __nv_bfloat162* kh = (__nv_bfloat162*)(g_kh + (size_t)bt * DD);
        __nv_bfloat162* kl = (__nv_bfloat162*)(g_kl + (size_t)bt * DD);
        const float LN_THETA = 9.210340371976184f;

        for (int pi = tid; pi < DD / 2; pi += 256) {
            int i = pi & 31;
            float inv = __expf(-((float)(2 * i) / 64.0f) * LN_THETA);
            float ang = p * inv;
            float s, c;
            sincosf(ang, &s, &c);
            int idx = 2 * pi;

            float qr = q[idx], qi = q[idx + 1];
            float qa = (qr * c - qi * s) * 0.125f;
            float qb = (qr * s + qi * c) * 0.125f;
            __nv_bfloat162 qh2 = __float22bfloat162_rn(make_float2(qa, qb));
            float2 qhb = __bfloat1622float2(qh2);
            qh[pi] = qh2;
            ql[pi] = __float22bfloat162_rn(make_float2(qa - qhb.x, qb - qhb.y));

            float kr = k[idx], ki = k[idx + 1];
            float ka = kr * c - ki * s;
            float kb = kr * s + ki * c;
            __nv_bfloat162 kh2 = __float22bfloat162_rn(make_float2(ka, kb));
            float2 khb = __bfloat1622float2(kh2);
            kh[pi] = kh2;
            kl[pi] = __float22bfloat162_rn(make_float2(ka - khb.x, kb - khb.y));
        }
    } else {
        const int vblk = blockIdx.x - MTOT;
        const int bh = vblk >> 5;
        const int b = bh >> 4, h = bh & 15;
        const int t0 = (vblk & 31) * 64;

#pragma unroll
        for (int i = 0; i < 4; i++) {
            int u = tid + 256 * i;
            int r = u >> 4, c4 = (u & 15) * 4;
            float4 v = *(const float4*)(g_v + (size_t)(b * TT + t0 + r) * DD + h * HD + c4);
            vs[r][c4] = v.x; vs[r][c4 + 1] = v.y; vs[r][c4 + 2] = v.z; vs[r][c4 + 3] = v.w;
        }
        __syncthreads();

#pragma unroll
        for (int i = 0; i < 8; i++) {
            int u = tid + 256 * i;
            int d = u >> 5, tp = u & 31;
            float f0 = vs[2 * tp][d], f1 = vs[2 * tp + 1][d];
            __nv_bfloat162 h2 = __float22bfloat162_rn(make_float2(f0, f1));
            float2 hb = __bfloat1622float2(h2);
            __nv_bfloat162 l2 = __float22bfloat162_rn(make_float2(f0 - hb.x, f1 - hb.y));
            size_t o = ((size_t)(b * 16 + h) * 64 + d) * 2048 + t0 + 2 * tp;
            *(__nv_bfloat162*)(g_vth + o) = h2;
            *(__nv_bfloat162*)(g_vtl + o) = l2;
        }
    }
}

// ===========================================================================
// Tensor-core flash attention, split-bf16, fixed-shift softmax.
// Epilogue writes bf16 hi/lo directly (g_aoh / g_aol).
// grid: (T/128, B*H), 256 threads; single sync per iter.
// ===========================================================================
#define AROWB 144
#define KTILE_B (64 * AROWB)
#define QTILE_B (128 * AROWB)
#define STG_OFF (2 * QTILE_B)
#define STG_B   (4 * KTILE_B)
#define ATTN2_SMEM (STG_OFF + 2 * STG_B)
#define SM_SHIFT 10.0f

__global__ __launch_bounds__(256) void attn_mma() {
    extern __shared__ char sm[];
    const uint32_t sb = smem_u32(sm);
    const int tid  = threadIdx.x;
    const int wid  = tid >> 5;
    const int lane = tid & 31;
    const int b = blockIdx.y >> 4, h = blockIdx.y & 15;
    const int q0 = blockIdx.x * 128;

#pragma unroll
    for (int i = 0; i < 8; i++) {
        int u = tid + 256 * i;
        int tens = u >> 10, r = (u >> 3) & 127, c = u & 7;
        const __nv_bfloat16* src = (tens ? g_ql : g_qh)
            + (size_t)(b * TT + q0 + r) * DD + h * HD + c * 8;
        *(uint4*)(sm + tens * QTILE_B + r * AROWB + c * 16) = *(const uint4*)src;
    }

    auto load_stage = [&](int kt, int s) {
        int k0 = kt * 64;
        uint32_t base = sb + STG_OFF + s * STG_B;
#pragma unroll
        for (int i = 0; i < 8; i++) {
            int u = tid + 256 * i;
            int tens = u >> 9, r = (u >> 3) & 63, c = u & 7;
            const __nv_bfloat16* src;
            if (tens == 0)      src = g_kh  + (size_t)(b * TT + k0 + r) * DD + h * HD + c * 8;
            else if (tens == 1) src = g_kl  + (size_t)(b * TT + k0 + r) * DD + h * HD + c * 8;
            else if (tens == 2) src = g_vth + ((size_t)(b * 16 + h) * 64 + r) * 2048 + k0 + c * 8;
            else                src = g_vtl + ((size_t)(b * 16 + h) * 64 + r) * 2048 + k0 + c * 8;
            CP_ASYNC16(base + tens * KTILE_B + r * AROWB + c * 16, src);
        }
        CP_COMMIT();
    };

    const int la7 = lane & 7;
    const int m8  = (lane >> 3) & 1, k8a = lane >> 4;
    const int n8  = lane >> 4,       k8b = (lane >> 3) & 1;

    float oacc[8][4];
#pragma unroll
    for (int j = 0; j < 8; j++)
#pragma unroll
        for (int e = 0; e < 4; e++) oacc[j][e] = 0.f;
    float rs0 = 0.f, rs1 = 0.f;

    load_stage(0, 0);

    for (int kt = 0; kt < 32; kt++) {
        CP_WAIT0();
        __syncthreads();
        if (kt < 31) load_stage(kt + 1, (kt + 1) & 1);

        uint32_t khB = sb + STG_OFF + (kt & 1) * STG_B;
        uint32_t klB = khB + KTILE_B;
        uint32_t vhB = khB + 2 * KTILE_B;
        uint32_t vlB = khB + 3 * KTILE_B;

        float sacc[8][4];
#pragma unroll
        for (int j = 0; j < 8; j++)
#pragma unroll
            for (int e = 0; e < 4; e++) sacc[j][e] = 0.f;

#pragma unroll
        for (int kc = 0; kc < 4; kc++) {
            uint32_t a_h[4], a_l[4];
            int arow = wid * 16 + m8 * 8 + la7;
            LDSM4(a_h, sb + arow * AROWB + k8a * 16 + kc * 32);
            LDSM4(a_l, sb + QTILE_B + arow * AROWB + k8a * 16 + kc * 32);
#pragma unroll
            for (int jp = 0; jp < 4; jp++) {
                int brow = jp * 16 + n8 * 8 + la7;
                uint32_t bh4[4], bl4[4];
                LDSM4(bh4, khB + brow * AROWB + k8b * 16 + kc * 32);
                LDSM4(bl4, klB + brow * AROWB + k8b * 16 + kc * 32);
                MMA16816(sacc[2 * jp],     a_h, bh4[0], bh4[1]);
                MMA16816(sacc[2 * jp + 1], a_h, bh4[2], bh4[3]);
                MMA16816(sacc[2 * jp],     a_h, bl4[0], bl4[1]);
                MMA16816(sacc[2 * jp + 1], a_h, bl4[2], bl4[3]);
                MMA16816(sacc[2 * jp],     a_l, bh4[0], bh4[1]);
                MMA16816(sacc[2 * jp + 1], a_l, bh4[2], bh4[3]);
            }
        }

#pragma unroll
        for (int j = 0; j < 8; j++) {
            sacc[j][0] = fexp(sacc[j][0] - SM_SHIFT);
            sacc[j][1] = fexp(sacc[j][1] - SM_SHIFT);
            sacc[j][2] = fexp(sacc[j][2] - SM_SHIFT);
            sacc[j][3] = fexp(sacc[j][3] - SM_SHIFT);
            rs0 += sacc[j][0] + sacc[j][1];
            rs1 += sacc[j][2] + sacc[j][3];
        }

#pragma unroll
        for (int kc = 0; kc < 4; kc++) {
            uint32_t ph[4], pl[4];
#pragma unroll
            for (int t = 0; t < 2; t++) {
                float f0 = sacc[2 * kc + t][0], f1 = sacc[2 * kc + t][1];
                float f2 = sacc[2 * kc + t][2], f3 = sacc[2 * kc + t][3];
                uint32_t h01 = pack_bf2(f0, f1);
                uint32_t h23 = pack_bf2(f2, f3);
                float2 b01 = __bfloat1622float2(*(__nv_bfloat162*)&h01);
                float2 b23 = __bfloat1622float2(*(__nv_bfloat162*)&h23);
                ph[2 * t]     = h01;
                ph[2 * t + 1] = h23;
                pl[2 * t]     = pack_bf2(f0 - b01.x, f1 - b01.y);
                pl[2 * t + 1] = pack_bf2(f2 - b23.x, f3 - b23.y);
            }
#pragma unroll
            for (int dj = 0; dj < 4; dj++) {
                int brow = dj * 16 + n8 * 8 + la7;
                uint32_t vh4[4], vl4[4];
                LDSM4(vh4, vhB + brow * AROWB + k8b * 16 + kc * 32);
                LDSM4(vl4, vlB + brow * AROWB + k8b * 16 + kc * 32);
                MMA16816(oacc[2 * dj],     ph, vh4[0], vh4[1]);
                MMA16816(oacc[2 * dj + 1], ph, vh4[2], vh4[3]);
                MMA16816(oacc[2 * dj],     ph, vl4[0], vl4[1]);
                MMA16816(oacc[2 * dj + 1], ph, vl4[2], vl4[3]);
                MMA16816(oacc[2 * dj],     pl, vh4[0], vh4[1]);
                MMA16816(oacc[2 * dj + 1], pl, vh4[2], vh4[3]);
            }
        }
    }

    rs0 += __shfl_xor_sync(0xffffffffu, rs0, 1);
    rs0 += __shfl_xor_sync(0xffffffffu, rs0, 2);
    rs1 += __shfl_xor_sync(0xffffffffu, rs1, 1);
    rs1 += __shfl_xor_sync(0xffffffffu, rs1, 2);
    float inv0 = 1.0f / rs0, inv1 = 1.0f / rs1;

    // epilogue: write bf16 hi/lo directly
    int r  = q0 + wid * 16 + (lane >> 2);
    int c0 = h * HD + (lane & 3) * 2;
#pragma unroll
    for (int j = 0; j < 8; j++) {
        float f0 = oacc[j][0] * inv0, f1 = oacc[j][1] * inv0;
        float f2 = oacc[j][2] * inv1, f3 = oacc[j][3] * inv1;
        size_t o0 = (size_t)(b * TT + r) * DD + c0 + 8 * j;
        size_t o1 = (size_t)(b * TT + r + 8) * DD + c0 + 8 * j;
        uint32_t h01 = pack_bf2(f0, f1);
        uint32_t h23 = pack_bf2(f2, f3);
        float2 b01 = __bfloat1622float2(*(__nv_bfloat162*)&h01);
        float2 b23 = __bfloat1622float2(*(__nv_bfloat162*)&h23);
        *(uint32_t*)(g_aoh + o0) = h01;
        *(uint32_t*)(g_aoh + o1) = h23;
        *(uint32_t*)(g_aol + o0) = pack_bf2(f0 - b01.x, f1 - b01.y);
        *(uint32_t*)(g_aol + o1) = pack_bf2(f2 - b23.x, f3 - b23.y);
    }
}

// ---------------------------------------------------------------------------
extern "C" void kernel_launch(void* const* d_in, const int* in_sizes, int n_in,
                              void* d_out, int out_size) {
    const float* x   = (const float*)d_in[0];
    const float* wq  = (const float*)d_in[1];
    const float* wk  = (const float*)d_in[2];
    const float* wv  = (const float*)d_in[3];
    const float* wo  = (const float*)d_in[4];
    const int*   pos = (const int*)  d_in[5];
    float* out = (float*)d_out;

    __nv_bfloat16 *xh, *xl, *aoh, *aol, *wh, *wl;
    float *q, *k, *v;
    cudaGetSymbolAddress((void**)&xh,  g_xh);
    cudaGetSymbolAddress((void**)&xl,  g_xl);
    cudaGetSymbolAddress((void**)&aoh, g_aoh);
    cudaGetSymbolAddress((void**)&aol, g_aol);
    cudaGetSymbolAddress((void**)&wh,  g_wh);
    cudaGetSymbolAddress((void**)&wl,  g_wl);
    cudaGetSymbolAddress((void**)&q,   g_q);
    cudaGetSymbolAddress((void**)&k,   g_k);
    cudaGetSymbolAddress((void**)&v,   g_v);

    cudaFuncSetAttribute(gemm_big, cudaFuncAttributeMaxDynamicSharedMemorySize, G2_SMEM);
    cudaFuncSetAttribute(attn_mma, cudaFuncAttributeMaxDynamicSharedMemorySize, ATTN2_SMEM);

    const int NW = DD * DD;

    // launch 0: all input splits fused
    split_all<<<(XU + 4 * WU) / 256, 256>>>(x, wq, wk, wv, wo);

    // launch 1: fused QKV projection (grid.z selects weight)
    gemm_big<<<dim3(8, 32, 3), 256, G2_SMEM>>>(xh, xl, wh, wl, q, k, v);

    // launch 2: rope + V transpose fused
    prep_kernel<<<MTOT + TT / 64 * BB * HH, 256>>>(pos);

    // launch 3: tensor-core flash attention (writes bf16 hi/lo)
    attn_mma<<<dim3(TT / 128, BB * HH), 256, ATTN2_SMEM>>>();

    // launch 4: output projection
    gemm_big<<<dim3(8, 32, 1), 256, G2_SMEM>>>(aoh, aol, wh + 3 * NW, wl + 3 * NW,
                                               out, out, out);
}